// round 1
// baseline (speedup 1.0000x reference)
#include <cuda_runtime.h>

// Problem constants
#define B_ 8
#define S_ 4096
#define E_ 256
#define H_ 64
#define DK_ 4

#define THREADS 512
#define TT_STRIDE 68          // [e][h] tile, padded
#define WC_STRIDE 257         // W chunk [o][k], padded

static constexpr int TT_FLOATS    = 256 * TT_STRIDE;   // 17408
static constexpr int UNION_FLOATS = 64 * WC_STRIDE;    // 16448 (>= 64*256 for qs)
static constexpr int SMEM_FLOATS  = TT_FLOATS + UNION_FLOATS;  // 33856 -> 135424 B

__global__ __launch_bounds__(THREADS, 1)
void mhaq_fused_kernel(const float* __restrict__ x,
                       const float* __restrict__ theta,
                       const float* __restrict__ W,
                       float* __restrict__ Y)
{
    extern __shared__ float sm[];
    float* Tt = sm;                 // [256][TT_STRIDE]  attention out, [e][h]
    float* qs = sm + TT_FLOATS;     // [64][256]         q vectors per token
    float* Wc = sm + TT_FLOATS;     // [64][WC_STRIDE]   W chunk (reuses qs region)

    const int g   = blockIdx.x;     // token group 0..63  (tokens s = 64g + r)
    const int b   = blockIdx.y;     // batch
    const int tid = threadIdx.x;

    const float t0 = __ldg(theta + 0);
    const float t1 = __ldg(theta + 1);
    const float t2 = __ldg(theta + 2);
    const float t3 = __ldg(theta + 3);

    // ---------------- Step A: qh = cumprod(cos(x + theta)) ----------------
    // 64 tokens x 64 heads = 4096 (r,h) pairs; 8 per thread.
    {
        const float* xg = x + ((size_t)b * S_ + (size_t)g * 64) * E_;
        #pragma unroll
        for (int i = 0; i < 8; i++) {
            int idx = tid + i * THREADS;       // 0..4095
            int r = idx >> 6;
            int h = idx & 63;
            float4 xv = *reinterpret_cast<const float4*>(xg + r * E_ + h * 4);
            float c0 = __cosf(xv.x + t0);
            float c1 = c0 * __cosf(xv.y + t1);
            float c2 = c1 * __cosf(xv.z + t2);
            float c3 = c2 * __cosf(xv.w + t3);
            float4 q = make_float4(c0, c1, c2, c3);
            *reinterpret_cast<float4*>(qs + r * E_ + h * 4) = q;
        }
    }
    __syncthreads();

    // ---------------- Step B: per-token attention over heads ----------------
    // Warp w handles tokens r = 4w .. 4w+3. Each lane owns rows h=lane and h=lane+32.
    // Scores s = 0.5 * dot(q_h, q_t) in [-2,2] -> softmax without max subtraction.
    {
        const int warp = tid >> 5;
        const int lane = tid & 31;
        for (int rr = warp * 4; rr < warp * 4 + 4; rr++) {
            const float* qrow = qs + rr * E_;
            float4 qA = *reinterpret_cast<const float4*>(qrow + lane * 4);
            float4 qB = *reinterpret_cast<const float4*>(qrow + (lane + 32) * 4);
            float aA0 = 0.f, aA1 = 0.f, aA2 = 0.f, aA3 = 0.f, lA = 0.f;
            float aB0 = 0.f, aB1 = 0.f, aB2 = 0.f, aB3 = 0.f, lB = 0.f;
            #pragma unroll 8
            for (int t = 0; t < 64; t++) {
                float4 qt = *reinterpret_cast<const float4*>(qrow + t * 4);  // broadcast
                float sA = 0.5f * (qA.x*qt.x + qA.y*qt.y + qA.z*qt.z + qA.w*qt.w);
                float sB = 0.5f * (qB.x*qt.x + qB.y*qt.y + qB.z*qt.z + qB.w*qt.w);
                float pA = __expf(sA);
                float pB = __expf(sB);
                lA += pA;  lB += pB;
                aA0 += pA * qt.x; aA1 += pA * qt.y; aA2 += pA * qt.z; aA3 += pA * qt.w;
                aB0 += pB * qt.x; aB1 += pB * qt.y; aB2 += pB * qt.z; aB3 += pB * qt.w;
            }
            float invA = 1.0f / lA;
            float invB = 1.0f / lB;
            // Store transposed: Tt[e][h], e = 4*rr + d. Lanes write consecutive h -> conflict-free.
            float* te = Tt + (rr * 4) * TT_STRIDE;
            te[0 * TT_STRIDE + lane]      = aA0 * invA;
            te[1 * TT_STRIDE + lane]      = aA1 * invA;
            te[2 * TT_STRIDE + lane]      = aA2 * invA;
            te[3 * TT_STRIDE + lane]      = aA3 * invA;
            te[0 * TT_STRIDE + lane + 32] = aB0 * invB;
            te[1 * TT_STRIDE + lane + 32] = aB1 * invB;
            te[2 * TT_STRIDE + lane + 32] = aB2 * invB;
            te[3 * TT_STRIDE + lane + 32] = aB3 * invB;
        }
    }

    // ---------------- Step C: epilogue GEMM  Y_tile = T @ W^T ----------------
    // T is [64 h][256 e] (stored transposed in Tt). W is [o][e] row-major.
    // 4 chunks of 64 output columns; per chunk stage W rows into Wc (padded).
    const int tx = tid & 63;        // o_local within chunk
    const int ty = tid >> 6;        // 0..7 -> rows h = ty*8 + i
    for (int oc = 0; oc < 4; oc++) {
        __syncthreads();            // Tt complete (first iter) / Wc consumers done (later iters)
        {
            const float* wsrc = W + (size_t)(oc * 64) * E_;   // 64 rows x 256
            #pragma unroll
            for (int i = tid; i < 64 * 64; i += THREADS) {    // 4096 float4s
                float4 wv = *reinterpret_cast<const float4*>(wsrc + i * 4);
                int o = (i * 4) >> 8;
                int k = (i * 4) & 255;
                float* dst = Wc + o * WC_STRIDE + k;
                dst[0] = wv.x; dst[1] = wv.y; dst[2] = wv.z; dst[3] = wv.w;
            }
        }
        __syncthreads();

        float acc[8];
        #pragma unroll
        for (int i = 0; i < 8; i++) acc[i] = 0.f;

        const float* wrow = Wc + tx * WC_STRIDE;
        #pragma unroll 4
        for (int k = 0; k < 256; k++) {
            float w = wrow[k];                                        // (tx+k)%32 banks: conflict-free
            const float* trow = Tt + k * TT_STRIDE + ty * 8;
            float4 a0 = *reinterpret_cast<const float4*>(trow);       // broadcast within warp
            float4 a1 = *reinterpret_cast<const float4*>(trow + 4);
            acc[0] += a0.x * w; acc[1] += a0.y * w;
            acc[2] += a0.z * w; acc[3] += a0.w * w;
            acc[4] += a1.x * w; acc[5] += a1.y * w;
            acc[6] += a1.z * w; acc[7] += a1.w * w;
        }

        const int o = oc * 64 + tx;
        #pragma unroll
        for (int i = 0; i < 8; i++) {
            int h = ty * 8 + i;
            // output row m = h*64 + g  (the "faithful torch" permuted layout)
            Y[((size_t)b * (S_) + (size_t)h * 64 + g) * E_ + o] = acc[i];
        }
    }
}

extern "C" void kernel_launch(void* const* d_in, const int* in_sizes, int n_in,
                              void* d_out, int out_size)
{
    const float* x     = (const float*)d_in[0];   // [8, 4096, 256]
    const float* theta = (const float*)d_in[1];   // [4]
    const float* W     = (const float*)d_in[2];   // [256, 256]
    float* Y           = (float*)d_out;           // [8, 4096, 256]

    size_t smem_bytes = (size_t)SMEM_FLOATS * sizeof(float);
    cudaFuncSetAttribute(mhaq_fused_kernel,
                         cudaFuncAttributeMaxDynamicSharedMemorySize,
                         (int)smem_bytes);

    dim3 grid(64, B_);   // 64 token-groups x 8 batches = 512 blocks
    mhaq_fused_kernel<<<grid, THREADS, smem_bytes>>>(x, theta, W, Y);
}